// round 2
// baseline (speedup 1.0000x reference)
#include <cuda_runtime.h>

#define EMBED   1280
#define NHEADS  32
#define HDIM    40
#define BSZV    2
#define TGT     1024
#define PAST    1024
#define SEQ     2048
#define SCALING 0.15811388300841897f

// Scratch (allocation-free): Q after projection [b,h,t,d], attention result [b,t,e]
__device__ float g_q[BSZV * NHEADS * TGT * HDIM];
__device__ float g_attn[BSZV * TGT * EMBED];

// ---------------------------------------------------------------------------
// Kernel 1: copy past K/V into the concat'd cache outputs
// ---------------------------------------------------------------------------
__global__ void copy_past_kernel(const float4* __restrict__ pk,
                                 const float4* __restrict__ pv,
                                 float4* __restrict__ ko,
                                 float4* __restrict__ vo) {
    const int total  = BSZV * NHEADS * PAST * HDIM / 4;   // 655360
    int i = blockIdx.x * blockDim.x + threadIdx.x;
    if (i >= total) return;
    const int per_bh = PAST * HDIM / 4;                   // 10240
    int bh = i / per_bh;
    int r  = i - bh * per_bh;
    int o  = bh * (SEQ * HDIM / 4) + r;
    ko[o] = pk[i];
    vo[o] = pv[i];
}

// ---------------------------------------------------------------------------
// Kernel 2: fused QKV projection GEMM (128x128x16 tiles, 8x8 micro).
// ---------------------------------------------------------------------------
__global__ __launch_bounds__(256) void gemm_qkv_kernel(
    const float* __restrict__ X,
    const float* __restrict__ Wq, const float* __restrict__ Wk, const float* __restrict__ Wv,
    const float* __restrict__ bq, const float* __restrict__ bk, const float* __restrict__ bv,
    float* __restrict__ k_out, float* __restrict__ v_out)
{
    __shared__ float As[16][132];   // transposed A tile, padded
    __shared__ float Bs[16][128];

    const int tid = threadIdx.x;
    const int m0  = blockIdx.x * 128;
    const int bn  = blockIdx.y;               // 0..29
    const int which = bn / 10;                // 0=Q,1=K,2=V
    const int n0  = (bn - which * 10) * 128;  // col within the weight matrix
    const float* __restrict__ W = (which == 0) ? Wq : ((which == 1) ? Wk : Wv);
    const int tx = tid & 15, ty = tid >> 4;

    float acc[8][8];
    #pragma unroll
    for (int i = 0; i < 8; i++)
        #pragma unroll
        for (int j = 0; j < 8; j++) acc[i][j] = 0.f;

    for (int k0 = 0; k0 < EMBED; k0 += 16) {
        #pragma unroll
        for (int i = 0; i < 2; i++) {
            int idx = tid + i * 256;          // 0..511
            int row = idx >> 2;               // 0..127
            int kq  = (idx & 3) << 2;         // 0,4,8,12
            float4 v = *reinterpret_cast<const float4*>(X + (m0 + row) * EMBED + k0 + kq);
            As[kq + 0][row] = v.x; As[kq + 1][row] = v.y;
            As[kq + 2][row] = v.z; As[kq + 3][row] = v.w;
        }
        #pragma unroll
        for (int i = 0; i < 2; i++) {
            int idx = tid + i * 256;
            int row = idx >> 5;               // 0..15
            int c4  = (idx & 31) << 2;        // 0..124
            *reinterpret_cast<float4*>(&Bs[row][c4]) =
                *reinterpret_cast<const float4*>(W + (k0 + row) * EMBED + n0 + c4);
        }
        __syncthreads();
        #pragma unroll
        for (int kk = 0; kk < 16; kk++) {
            float a[8], b[8];
            *reinterpret_cast<float4*>(a)     = *reinterpret_cast<const float4*>(&As[kk][ty * 8]);
            *reinterpret_cast<float4*>(a + 4) = *reinterpret_cast<const float4*>(&As[kk][ty * 8 + 4]);
            *reinterpret_cast<float4*>(b)     = *reinterpret_cast<const float4*>(&Bs[kk][tx * 8]);
            *reinterpret_cast<float4*>(b + 4) = *reinterpret_cast<const float4*>(&Bs[kk][tx * 8 + 4]);
            #pragma unroll
            for (int i = 0; i < 8; i++)
                #pragma unroll
                for (int j = 0; j < 8; j++)
                    acc[i][j] = fmaf(a[i], b[j], acc[i][j]);
        }
        __syncthreads();
    }

    #pragma unroll
    for (int i = 0; i < 8; i++) {
        int m = m0 + ty * 8 + i;
        int b = m >> 10;
        int t = m & 1023;
        #pragma unroll
        for (int j = 0; j < 8; j++) {
            int e = n0 + tx * 8 + j;
            int h = e / HDIM;
            int d = e - h * HDIM;
            float v = acc[i][j];
            if (which == 0) {
                g_q[((b * NHEADS + h) * TGT + t) * HDIM + d] = (v + bq[e]) * SCALING;
            } else if (which == 1) {
                k_out[((b * NHEADS + h) * SEQ + PAST + t) * HDIM + d] = v + bk[e];
            } else {
                v_out[((b * NHEADS + h) * SEQ + PAST + t) * HDIM + d] = v + bv[e];
            }
        }
    }
}

// ---------------------------------------------------------------------------
// Kernel 3: flash-style attention. Writes g_attn directly (device symbol).
// ---------------------------------------------------------------------------
__global__ __launch_bounds__(256) void attn_kernel(
    const float* __restrict__ Kc,   // key_states [b,h,2048,40]
    const float* __restrict__ Vc)   // value_states
{
    __shared__ float Qs[64][41];
    __shared__ float Ks[64][41];
    __shared__ float Vs[64][41];
    __shared__ float Ps[64][64];

    const int bh = blockIdx.x;            // 0..63
    const int qt = blockIdx.y;            // 0..15
    const int b  = bh >> 5, h = bh & 31;
    const int tid = threadIdx.x;
    const int tx = tid & 15, ty = tid >> 4;
    const int cg    = (tx & 7) * 5;       // owned O column group base
    const int khalf = (tx >> 3) * 32;     // key half for PV

    const float* Qb = g_q + (bh * TGT + qt * 64) * HDIM;
    for (int i = tid; i < 64 * HDIM; i += 256) {
        int r = i / HDIM, c = i - r * HDIM;
        Qs[r][c] = Qb[i];
    }

    float m_r[4], l_r[4], o[4][5];
    #pragma unroll
    for (int i = 0; i < 4; i++) {
        m_r[i] = -1e30f; l_r[i] = 0.f;
        #pragma unroll
        for (int u = 0; u < 5; u++) o[i][u] = 0.f;
    }

    for (int j = 0; j < SEQ / 64; j++) {
        __syncthreads();   // prior PV done; Qs load done (iter 0)
        const float* Kb = Kc + (bh * SEQ + j * 64) * HDIM;
        const float* Vb = Vc + (bh * SEQ + j * 64) * HDIM;
        for (int i = tid; i < 64 * HDIM; i += 256) {
            int r = i / HDIM, c = i - r * HDIM;
            Ks[r][c] = Kb[i];
            Vs[r][c] = Vb[i];
        }
        __syncthreads();

        float s[4][4];
        #pragma unroll
        for (int i = 0; i < 4; i++)
            #pragma unroll
            for (int c = 0; c < 4; c++) s[i][c] = 0.f;

        #pragma unroll 8
        for (int kk = 0; kk < HDIM; kk++) {
            float qv[4], kv[4];
            #pragma unroll
            for (int i = 0; i < 4; i++) { qv[i] = Qs[ty * 4 + i][kk]; kv[i] = Ks[tx * 4 + i][kk]; }
            #pragma unroll
            for (int i = 0; i < 4; i++)
                #pragma unroll
                for (int c = 0; c < 4; c++)
                    s[i][c] = fmaf(qv[i], kv[c], s[i][c]);
        }

        // online softmax update (per-row across the 16 tx lanes, shfl width 16)
        #pragma unroll
        for (int i = 0; i < 4; i++) {
            float mx = fmaxf(fmaxf(s[i][0], s[i][1]), fmaxf(s[i][2], s[i][3]));
            #pragma unroll
            for (int off = 8; off; off >>= 1)
                mx = fmaxf(mx, __shfl_xor_sync(0xffffffffu, mx, off, 16));
            float m_new = fmaxf(m_r[i], mx);
            float corr  = __expf(m_r[i] - m_new);
            m_r[i] = m_new;
            float ls = 0.f;
            #pragma unroll
            for (int c = 0; c < 4; c++) { s[i][c] = __expf(s[i][c] - m_new); ls += s[i][c]; }
            #pragma unroll
            for (int off = 8; off; off >>= 1)
                ls += __shfl_xor_sync(0xffffffffu, ls, off, 16);
            l_r[i] = l_r[i] * corr + ls;
            #pragma unroll
            for (int u = 0; u < 5; u++) o[i][u] *= corr;
        }

        #pragma unroll
        for (int i = 0; i < 4; i++)
            #pragma unroll
            for (int c = 0; c < 4; c++)
                Ps[ty * 4 + i][tx * 4 + c] = s[i][c];
        __syncthreads();

        // PV: each thread accumulates 32 keys (its half) over its 5 columns
        #pragma unroll 8
        for (int kk = 0; kk < 32; kk++) {
            int k = khalf + kk;
            float p[4];
            #pragma unroll
            for (int i = 0; i < 4; i++) p[i] = Ps[ty * 4 + i][k];
            float v0 = Vs[k][cg + 0], v1 = Vs[k][cg + 1], v2 = Vs[k][cg + 2],
                  v3 = Vs[k][cg + 3], v4 = Vs[k][cg + 4];
            #pragma unroll
            for (int i = 0; i < 4; i++) {
                o[i][0] = fmaf(p[i], v0, o[i][0]);
                o[i][1] = fmaf(p[i], v1, o[i][1]);
                o[i][2] = fmaf(p[i], v2, o[i][2]);
                o[i][3] = fmaf(p[i], v3, o[i][3]);
                o[i][4] = fmaf(p[i], v4, o[i][4]);
            }
        }
    }

    // combine key halves (tx ^ 8) and write
    #pragma unroll
    for (int i = 0; i < 4; i++)
        #pragma unroll
        for (int u = 0; u < 5; u++)
            o[i][u] += __shfl_xor_sync(0xffffffffu, o[i][u], 8, 16);

    if (tx < 8) {
        #pragma unroll
        for (int i = 0; i < 4; i++) {
            int t = qt * 64 + ty * 4 + i;
            float inv = 1.0f / l_r[i];
            float* dst = g_attn + (b * TGT + t) * EMBED + h * HDIM + cg;
            #pragma unroll
            for (int u = 0; u < 5; u++) dst[u] = o[i][u] * inv;
        }
    }
}

// ---------------------------------------------------------------------------
// Kernel 4: output projection GEMM. A = g_attn [2048,1280], W = Wo, +bo.
// ---------------------------------------------------------------------------
__global__ __launch_bounds__(256) void gemm_out_kernel(
    const float* __restrict__ W, const float* __restrict__ bo,
    float* __restrict__ out)
{
    __shared__ float As[16][132];
    __shared__ float Bs[16][128];

    const int tid = threadIdx.x;
    const int m0  = blockIdx.x * 128;
    const int n0  = blockIdx.y * 128;
    const int tx = tid & 15, ty = tid >> 4;

    float acc[8][8];
    #pragma unroll
    for (int i = 0; i < 8; i++)
        #pragma unroll
        for (int j = 0; j < 8; j++) acc[i][j] = 0.f;

    for (int k0 = 0; k0 < EMBED; k0 += 16) {
        #pragma unroll
        for (int i = 0; i < 2; i++) {
            int idx = tid + i * 256;
            int row = idx >> 2;
            int kq  = (idx & 3) << 2;
            float4 v = *reinterpret_cast<const float4*>(g_attn + (m0 + row) * EMBED + k0 + kq);
            As[kq + 0][row] = v.x; As[kq + 1][row] = v.y;
            As[kq + 2][row] = v.z; As[kq + 3][row] = v.w;
        }
        #pragma unroll
        for (int i = 0; i < 2; i++) {
            int idx = tid + i * 256;
            int row = idx >> 5;
            int c4  = (idx & 31) << 2;
            *reinterpret_cast<float4*>(&Bs[row][c4]) =
                *reinterpret_cast<const float4*>(W + (k0 + row) * EMBED + n0 + c4);
        }
        __syncthreads();
        #pragma unroll
        for (int kk = 0; kk < 16; kk++) {
            float a[8], b[8];
            *reinterpret_cast<float4*>(a)     = *reinterpret_cast<const float4*>(&As[kk][ty * 8]);
            *reinterpret_cast<float4*>(a + 4) = *reinterpret_cast<const float4*>(&As[kk][ty * 8 + 4]);
            *reinterpret_cast<float4*>(b)     = *reinterpret_cast<const float4*>(&Bs[kk][tx * 8]);
            *reinterpret_cast<float4*>(b + 4) = *reinterpret_cast<const float4*>(&Bs[kk][tx * 8 + 4]);
            #pragma unroll
            for (int i = 0; i < 8; i++)
                #pragma unroll
                for (int j = 0; j < 8; j++)
                    acc[i][j] = fmaf(a[i], b[j], acc[i][j]);
        }
        __syncthreads();
    }

    #pragma unroll
    for (int i = 0; i < 8; i++) {
        int m = m0 + ty * 8 + i;
        #pragma unroll
        for (int j = 0; j < 8; j++) {
            int e = n0 + tx * 8 + j;
            out[m * EMBED + e] = acc[i][j] + bo[e];
        }
    }
}

// ---------------------------------------------------------------------------
extern "C" void kernel_launch(void* const* d_in, const int* in_sizes, int n_in,
                              void* d_out, int out_size) {
    const float* X  = (const float*)d_in[0];
    const float* pk = (const float*)d_in[1];
    const float* pv = (const float*)d_in[2];
    const float* Wq = (const float*)d_in[3];
    const float* bq = (const float*)d_in[4];
    const float* Wk = (const float*)d_in[5];
    const float* bk = (const float*)d_in[6];
    const float* Wv = (const float*)d_in[7];
    const float* bv = (const float*)d_in[8];
    const float* Wo = (const float*)d_in[9];
    const float* bo = (const float*)d_in[10];

    float* out      = (float*)d_out;
    float* attn_out = out;                                   // [2,1024,1280]
    float* k_out    = out + (size_t)BSZV * TGT * EMBED;      // [2,32,2048,40]
    float* v_out    = k_out + (size_t)BSZV * NHEADS * SEQ * HDIM;

    // 1) copy past KV into concat output
    {
        int total = BSZV * NHEADS * PAST * HDIM / 4;
        copy_past_kernel<<<(total + 255) / 256, 256>>>(
            (const float4*)pk, (const float4*)pv, (float4*)k_out, (float4*)v_out);
    }
    // 2) fused QKV projection
    {
        dim3 grid(BSZV * TGT / 128, 30);
        gemm_qkv_kernel<<<grid, 256>>>(X, Wq, Wk, Wv, bq, bk, bv, k_out, v_out);
    }
    // 3) attention (reads g_q, writes g_attn internally)
    {
        dim3 grid(BSZV * NHEADS, TGT / 64);
        attn_kernel<<<grid, 256>>>(k_out, v_out);
    }
    // 4) output projection
    {
        dim3 grid(BSZV * TGT / 128, EMBED / 128);
        gemm_out_kernel<<<grid, 256>>>(Wo, bo, attn_out);
    }
}

// round 7
// speedup vs baseline: 1.3334x; 1.3334x over previous
#include <cuda_runtime.h>
#include <cuda_bf16.h>
#include <cstdint>

#define EMBED   1280
#define NHEADS  32
#define HDIM    40
#define BSZV    2
#define TGT     1024
#define PAST    1024
#define SEQ     2048
#define SCALING 0.15811388300841897f

#define KP      3840                  // K' = 3*1280 (bf16x3 concatenated K)
#define KC      64                    // K chunk (64 bf16 = 128B data per row)
#define NCH     (KP / KC)             // 60
#define ROWB    144                   // 128B data + 16B pad (36 words; conflict-free)

// ---------------------------------------------------------------------------
// device scratch
// ---------------------------------------------------------------------------
__device__ __align__(256) float g_q[BSZV * NHEADS * TGT * HDIM];
__device__ __align__(256) float g_attn[BSZV * TGT * EMBED];
__device__ __align__(256) __nv_bfloat16 g_Ax[2048 * KP];
__device__ __align__(256) __nv_bfloat16 g_Aattn[2048 * KP];
__device__ __align__(256) __nv_bfloat16 g_Bqkv[3840 * KP];
__device__ __align__(256) __nv_bfloat16 g_Bo[1280 * KP];

// ---------------------------------------------------------------------------
// mma.sync (register-only HMMA)
// ---------------------------------------------------------------------------
__device__ __forceinline__ void mma16816(float* d, const uint32_t* a, const uint32_t* b) {
    asm volatile(
        "mma.sync.aligned.m16n8k16.row.col.f32.bf16.bf16.f32 "
        "{%0,%1,%2,%3}, {%4,%5,%6,%7}, {%8,%9}, {%0,%1,%2,%3};"
        : "+f"(d[0]), "+f"(d[1]), "+f"(d[2]), "+f"(d[3])
        : "r"(a[0]), "r"(a[1]), "r"(a[2]), "r"(a[3]), "r"(b[0]), "r"(b[1]));
}

// ---------------------------------------------------------------------------
// conversion kernels (bf16x3 splitting). NOTE: device symbols are referenced
// ONLY inside kernels — never passed from host.
// ---------------------------------------------------------------------------
__device__ __forceinline__ void split_row(__nv_bfloat16* row, int k, float x) {
    __nv_bfloat16 hi = __float2bfloat16(x);
    __nv_bfloat16 lo = __float2bfloat16(x - __bfloat162float(hi));
    row[k] = hi; row[1280 + k] = hi; row[2560 + k] = lo;
}

__global__ void conv_split_X(const float* __restrict__ src) {
    int i = blockIdx.x * blockDim.x + threadIdx.x;
    if (i >= 2048 * 1280) return;
    int m = i / 1280, k = i - m * 1280;
    split_row(g_Ax + (size_t)m * KP, k, src[i]);
}

__global__ void conv_split_attn() {
    int i = blockIdx.x * blockDim.x + threadIdx.x;
    if (i >= 2048 * 1280) return;
    int m = i / 1280, k = i - m * 1280;
    split_row(g_Aattn + (size_t)m * KP, k, g_attn[i]);
}

__global__ void conv_w_kernel(const float* __restrict__ W, int sel) {
    // W [1280 k, 1280 e] -> B' row n=e: [k]=hi, [1280+k]=lo, [2560+k]=hi
    __shared__ float s[32][33];
    __nv_bfloat16* dst = (sel < 3) ? (g_Bqkv + (size_t)sel * 1280 * KP) : g_Bo;
    int e0 = blockIdx.x * 32, k0 = blockIdx.y * 32;
    int tx = threadIdx.x, ty = threadIdx.y;
    #pragma unroll
    for (int j = 0; j < 4; j++)
        s[ty + j * 8][tx] = W[(k0 + ty + j * 8) * 1280 + e0 + tx];
    __syncthreads();
    #pragma unroll
    for (int j = 0; j < 4; j++) {
        float x = s[tx][ty + j * 8];           // = W[k0+tx][e0+ty+j*8]
        __nv_bfloat16 hi = __float2bfloat16(x);
        __nv_bfloat16 lo = __float2bfloat16(x - __bfloat162float(hi));
        __nv_bfloat16* row = dst + (size_t)(e0 + ty + j * 8) * KP;
        row[k0 + tx] = hi; row[1280 + k0 + tx] = lo; row[2560 + k0 + tx] = hi;
    }
}

// ---------------------------------------------------------------------------
// HMMA mainloop: acc[2][8][4] += A'[m0:+128,:] * B'[n0:+128,:]^T
// 8 warps: warp (wm=w&3, wn=w>>2) owns 32(M) x 64(N).
// ---------------------------------------------------------------------------
__device__ __forceinline__ uint32_t lds32(const char* p) {
    return *reinterpret_cast<const uint32_t*>(p);
}

__device__ __forceinline__ void mma_tile(
    const __nv_bfloat16* __restrict__ A, const __nv_bfloat16* __restrict__ B,
    int m0, int n0, char* smA, char* smB, float acc[2][8][4])
{
    const int tid = threadIdx.x, lane = tid & 31, w = tid >> 5;
    const int wm = w & 3, wn = w >> 2;

    for (int c = 0; c < NCH; c++) {
        #pragma unroll
        for (int i = 0; i < 4; i++) {
            int idx = tid + i * 256;
            int r = idx >> 3, u = idx & 7;
            *reinterpret_cast<float4*>(smA + r * ROWB + u * 16) =
                *reinterpret_cast<const float4*>(A + (size_t)(m0 + r) * KP + c * KC + u * 8);
            *reinterpret_cast<float4*>(smB + r * ROWB + u * 16) =
                *reinterpret_cast<const float4*>(B + (size_t)(n0 + r) * KP + c * KC + u * 8);
        }
        __syncthreads();

        #pragma unroll
        for (int ks = 0; ks < 4; ks++) {
            const int acol2 = (ks * 16 + (lane & 3) * 2) * 2;
            #pragma unroll
            for (int mi = 0; mi < 2; mi++) {
                uint32_t af[4];
                const int ar = wm * 32 + mi * 16 + (lane >> 2);
                af[0] = lds32(smA + ar * ROWB + acol2);
                af[1] = lds32(smA + (ar + 8) * ROWB + acol2);
                af[2] = lds32(smA + ar * ROWB + acol2 + 16);
                af[3] = lds32(smA + (ar + 8) * ROWB + acol2 + 16);
                #pragma unroll
                for (int nb = 0; nb < 4; nb++) {
                    const int br = wn * 64 + nb * 16 + (lane >> 2);
                    uint32_t bf[4];
                    bf[0] = lds32(smB + br * ROWB + acol2);
                    bf[1] = lds32(smB + br * ROWB + acol2 + 16);
                    bf[2] = lds32(smB + (br + 8) * ROWB + acol2);
                    bf[3] = lds32(smB + (br + 8) * ROWB + acol2 + 16);
                    mma16816(acc[mi][2 * nb],     af, bf);
                    mma16816(acc[mi][2 * nb + 1], af, bf + 2);
                }
            }
        }
        __syncthreads();
    }
}

// ---------------------------------------------------------------------------
// GEMM kernel A: fused QKV projection. grid (16, 30)
// ---------------------------------------------------------------------------
__global__ __launch_bounds__(256)
void gemm_qkv_mma(const float* __restrict__ bq, const float* __restrict__ bk,
                  const float* __restrict__ bv,
                  float* __restrict__ k_out, float* __restrict__ v_out)
{
    __shared__ __align__(16) char smA[128 * ROWB];
    __shared__ __align__(16) char smB[128 * ROWB];
    float acc[2][8][4];
    #pragma unroll
    for (int i = 0; i < 2; i++)
        #pragma unroll
        for (int j = 0; j < 8; j++)
            #pragma unroll
            for (int r = 0; r < 4; r++) acc[i][j][r] = 0.f;

    const int m0 = blockIdx.x * 128;
    mma_tile(g_Ax, g_Bqkv, m0, blockIdx.y * 128, smA, smB, acc);

    const int lane = threadIdx.x & 31, w = threadIdx.x >> 5;
    const int wm = w & 3, wn = w >> 2;
    const int which = blockIdx.y / 10;
    const int ebase = (blockIdx.y % 10) * 128 + wn * 64;

    #pragma unroll
    for (int mi = 0; mi < 2; mi++)
        #pragma unroll
        for (int ni = 0; ni < 8; ni++)
            #pragma unroll
            for (int r = 0; r < 4; r++) {
                int m = m0 + wm * 32 + mi * 16 + (lane >> 2) + ((r >> 1) & 1) * 8;
                int e = ebase + ni * 8 + (lane & 3) * 2 + (r & 1);
                int bb = m >> 10, t = m & 1023;
                int h = e / HDIM, d = e - h * HDIM;
                float v = acc[mi][ni][r];
                if (which == 0)
                    g_q[((bb * NHEADS + h) * TGT + t) * HDIM + d] = (v + bq[e]) * SCALING;
                else if (which == 1)
                    k_out[((bb * NHEADS + h) * SEQ + PAST + t) * HDIM + d] = v + bk[e];
                else
                    v_out[((bb * NHEADS + h) * SEQ + PAST + t) * HDIM + d] = v + bv[e];
            }
}

// ---------------------------------------------------------------------------
// GEMM kernel B: output projection. grid (16, 10)
// ---------------------------------------------------------------------------
__global__ __launch_bounds__(256)
void gemm_out_mma(const float* __restrict__ bo, float* __restrict__ out)
{
    __shared__ __align__(16) char smA[128 * ROWB];
    __shared__ __align__(16) char smB[128 * ROWB];
    float acc[2][8][4];
    #pragma unroll
    for (int i = 0; i < 2; i++)
        #pragma unroll
        for (int j = 0; j < 8; j++)
            #pragma unroll
            for (int r = 0; r < 4; r++) acc[i][j][r] = 0.f;

    const int m0 = blockIdx.x * 128;
    const int n0 = blockIdx.y * 128;
    mma_tile(g_Aattn, g_Bo, m0, n0, smA, smB, acc);

    const int lane = threadIdx.x & 31, w = threadIdx.x >> 5;
    const int wm = w & 3, wn = w >> 2;

    #pragma unroll
    for (int mi = 0; mi < 2; mi++)
        #pragma unroll
        for (int ni = 0; ni < 8; ni++)
            #pragma unroll
            for (int r = 0; r < 4; r++) {
                int m = m0 + wm * 32 + mi * 16 + (lane >> 2) + ((r >> 1) & 1) * 8;
                int e = n0 + wn * 64 + ni * 8 + (lane & 3) * 2 + (r & 1);
                out[(size_t)m * EMBED + e] = acc[mi][ni][r] + bo[e];
            }
}

// ---------------------------------------------------------------------------
// past K/V copy
// ---------------------------------------------------------------------------
__global__ void copy_past_kernel(const float4* __restrict__ pk,
                                 const float4* __restrict__ pv,
                                 float4* __restrict__ ko,
                                 float4* __restrict__ vo) {
    const int total  = BSZV * NHEADS * PAST * HDIM / 4;
    int i = blockIdx.x * blockDim.x + threadIdx.x;
    if (i >= total) return;
    const int per_bh = PAST * HDIM / 4;
    int bh = i / per_bh;
    int r  = i - bh * per_bh;
    int o  = bh * (SEQ * HDIM / 4) + r;
    ko[o] = pk[i];
    vo[o] = pv[i];
}

// ---------------------------------------------------------------------------
// flash attention (fp32 SIMT) — reads g_q, writes g_attn (device symbols)
// ---------------------------------------------------------------------------
__global__ __launch_bounds__(256) void attn_kernel(
    const float* __restrict__ Kc, const float* __restrict__ Vc)
{
    __shared__ float Qs[64][41];
    __shared__ float Ks[64][41];
    __shared__ float Vs[64][41];
    __shared__ float Ps[64][64];

    const int bh = blockIdx.x;
    const int qt = blockIdx.y;
    const int b  = bh >> 5, h = bh & 31;
    const int tid = threadIdx.x;
    const int tx = tid & 15, ty = tid >> 4;
    const int cg    = (tx & 7) * 5;
    const int khalf = (tx >> 3) * 32;

    const float* Qb = g_q + (bh * TGT + qt * 64) * HDIM;
    for (int i = tid; i < 64 * HDIM; i += 256) {
        int r = i / HDIM, c = i - r * HDIM;
        Qs[r][c] = Qb[i];
    }

    float m_r[4], l_r[4], o[4][5];
    #pragma unroll
    for (int i = 0; i < 4; i++) {
        m_r[i] = -1e30f; l_r[i] = 0.f;
        #pragma unroll
        for (int u = 0; u < 5; u++) o[i][u] = 0.f;
    }

    for (int j = 0; j < SEQ / 64; j++) {
        __syncthreads();
        const float* Kb = Kc + (bh * SEQ + j * 64) * HDIM;
        const float* Vb = Vc + (bh * SEQ + j * 64) * HDIM;
        for (int i = tid; i < 64 * HDIM; i += 256) {
            int r = i / HDIM, c = i - r * HDIM;
            Ks[r][c] = Kb[i];
            Vs[r][c] = Vb[i];
        }
        __syncthreads();

        float s[4][4];
        #pragma unroll
        for (int i = 0; i < 4; i++)
            #pragma unroll
            for (int c = 0; c < 4; c++) s[i][c] = 0.f;

        #pragma unroll 8
        for (int kk = 0; kk < HDIM; kk++) {
            float qv[4], kv[4];
            #pragma unroll
            for (int i = 0; i < 4; i++) { qv[i] = Qs[ty * 4 + i][kk]; kv[i] = Ks[tx * 4 + i][kk]; }
            #pragma unroll
            for (int i = 0; i < 4; i++)
                #pragma unroll
                for (int c = 0; c < 4; c++)
                    s[i][c] = fmaf(qv[i], kv[c], s[i][c]);
        }

        #pragma unroll
        for (int i = 0; i < 4; i++) {
            float mx = fmaxf(fmaxf(s[i][0], s[i][1]), fmaxf(s[i][2], s[i][3]));
            #pragma unroll
            for (int off = 8; off; off >>= 1)
                mx = fmaxf(mx, __shfl_xor_sync(0xffffffffu, mx, off, 16));
            float m_new = fmaxf(m_r[i], mx);
            float corr  = __expf(m_r[i] - m_new);
            m_r[i] = m_new;
            float ls = 0.f;
            #pragma unroll
            for (int c = 0; c < 4; c++) { s[i][c] = __expf(s[i][c] - m_new); ls += s[i][c]; }
            #pragma unroll
            for (int off = 8; off; off >>= 1)
                ls += __shfl_xor_sync(0xffffffffu, ls, off, 16);
            l_r[i] = l_r[i] * corr + ls;
            #pragma unroll
            for (int u = 0; u < 5; u++) o[i][u] *= corr;
        }

        #pragma unroll
        for (int i = 0; i < 4; i++)
            #pragma unroll
            for (int c = 0; c < 4; c++)
                Ps[ty * 4 + i][tx * 4 + c] = s[i][c];
        __syncthreads();

        #pragma unroll 8
        for (int kk = 0; kk < 32; kk++) {
            int k = khalf + kk;
            float p[4];
            #pragma unroll
            for (int i = 0; i < 4; i++) p[i] = Ps[ty * 4 + i][k];
            float v0 = Vs[k][cg + 0], v1 = Vs[k][cg + 1], v2 = Vs[k][cg + 2],
                  v3 = Vs[k][cg + 3], v4 = Vs[k][cg + 4];
            #pragma unroll
            for (int i = 0; i < 4; i++) {
                o[i][0] = fmaf(p[i], v0, o[i][0]);
                o[i][1] = fmaf(p[i], v1, o[i][1]);
                o[i][2] = fmaf(p[i], v2, o[i][2]);
                o[i][3] = fmaf(p[i], v3, o[i][3]);
                o[i][4] = fmaf(p[i], v4, o[i][4]);
            }
        }
    }

    #pragma unroll
    for (int i = 0; i < 4; i++)
        #pragma unroll
        for (int u = 0; u < 5; u++)
            o[i][u] += __shfl_xor_sync(0xffffffffu, o[i][u], 8, 16);

    if (tx < 8) {
        #pragma unroll
        for (int i = 0; i < 4; i++) {
            int t = qt * 64 + ty * 4 + i;
            float inv = 1.0f / l_r[i];
            float* dst = g_attn + (b * TGT + t) * EMBED + h * HDIM + cg;
            #pragma unroll
            for (int u = 0; u < 5; u++) dst[u] = o[i][u] * inv;
        }
    }
}

// ---------------------------------------------------------------------------
extern "C" void kernel_launch(void* const* d_in, const int* in_sizes, int n_in,
                              void* d_out, int out_size) {
    const float* X  = (const float*)d_in[0];
    const float* pk = (const float*)d_in[1];
    const float* pv = (const float*)d_in[2];
    const float* Wq = (const float*)d_in[3];
    const float* bq = (const float*)d_in[4];
    const float* Wk = (const float*)d_in[5];
    const float* bk = (const float*)d_in[6];
    const float* Wv = (const float*)d_in[7];
    const float* bv = (const float*)d_in[8];
    const float* Wo = (const float*)d_in[9];
    const float* bo = (const float*)d_in[10];

    float* out      = (float*)d_out;
    float* attn_out = out;
    float* k_out    = out + (size_t)BSZV * TGT * EMBED;
    float* v_out    = k_out + (size_t)BSZV * NHEADS * SEQ * HDIM;

    // 1) past KV copy
    {
        int total = BSZV * NHEADS * PAST * HDIM / 4;
        copy_past_kernel<<<(total + 255) / 256, 256>>>(
            (const float4*)pk, (const float4*)pv, (float4*)k_out, (float4*)v_out);
    }
    // 2) conversions
    conv_split_X<<<(2048 * 1280 + 255) / 256, 256>>>(X);
    {
        dim3 g(40, 40), b2(32, 8);
        conv_w_kernel<<<g, b2>>>(Wq, 0);
        conv_w_kernel<<<g, b2>>>(Wk, 1);
        conv_w_kernel<<<g, b2>>>(Wv, 2);
        conv_w_kernel<<<g, b2>>>(Wo, 3);
    }
    // 3) fused QKV projection on tensor cores (mma.sync)
    gemm_qkv_mma<<<dim3(16, 30), 256>>>(bq, bk, bv, k_out, v_out);
    // 4) attention (fp32 SIMT)
    attn_kernel<<<dim3(BSZV * NHEADS, TGT / 64), 256>>>(k_out, v_out);
    // 5) convert attention result, output projection
    conv_split_attn<<<(2048 * 1280 + 255) / 256, 256>>>();
    gemm_out_mma<<<dim3(16, 10), 256>>>(bo, attn_out);
}

// round 8
// speedup vs baseline: 2.4661x; 1.8494x over previous
#include <cuda_runtime.h>
#include <cuda_bf16.h>
#include <cuda_fp16.h>
#include <cstdint>

#define EMBED   1280
#define NHEADS  32
#define HDIM    40
#define BSZV    2
#define TGT     1024
#define PAST    1024
#define SEQ     2048
#define SCALING 0.15811388300841897f

#define KP      3840                  // K' = 3*1280 (bf16x3 concatenated K)
#define KC      64                    // GEMM K chunk
#define NCH     (KP / KC)             // 60
#define ROWB    144                   // GEMM smem row bytes

// ---------------------------------------------------------------------------
// device scratch
// ---------------------------------------------------------------------------
__device__ __align__(256) float g_q[BSZV * NHEADS * TGT * HDIM];
__device__ __align__(256) float g_attn[BSZV * TGT * EMBED];
__device__ __align__(256) __nv_bfloat16 g_Ax[2048 * KP];
__device__ __align__(256) __nv_bfloat16 g_Aattn[2048 * KP];
__device__ __align__(256) __nv_bfloat16 g_Bqkv[3840 * KP];
__device__ __align__(256) __nv_bfloat16 g_Bo[1280 * KP];
__device__ __align__(256) __half g_Kh[64 * 2048 * 48];   // K cache fp16, [bh][key][48]
__device__ __align__(256) __half g_Vt[64 * 48 * 2048];   // V^T fp16,    [bh][dim48][key]

// ---------------------------------------------------------------------------
// mma.sync helpers (register-only)
// ---------------------------------------------------------------------------
__device__ __forceinline__ void mma16816(float* d, const uint32_t* a, const uint32_t* b) {
    asm volatile(
        "mma.sync.aligned.m16n8k16.row.col.f32.bf16.bf16.f32 "
        "{%0,%1,%2,%3}, {%4,%5,%6,%7}, {%8,%9}, {%0,%1,%2,%3};"
        : "+f"(d[0]), "+f"(d[1]), "+f"(d[2]), "+f"(d[3])
        : "r"(a[0]), "r"(a[1]), "r"(a[2]), "r"(a[3]), "r"(b[0]), "r"(b[1]));
}
__device__ __forceinline__ void mma16816h(float* d, const uint32_t* a, const uint32_t* b) {
    asm volatile(
        "mma.sync.aligned.m16n8k16.row.col.f32.f16.f16.f32 "
        "{%0,%1,%2,%3}, {%4,%5,%6,%7}, {%8,%9}, {%0,%1,%2,%3};"
        : "+f"(d[0]), "+f"(d[1]), "+f"(d[2]), "+f"(d[3])
        : "r"(a[0]), "r"(a[1]), "r"(a[2]), "r"(a[3]), "r"(b[0]), "r"(b[1]));
}
__device__ __forceinline__ uint32_t packh(float x, float y) {
    __half2 h = __halves2half2(__float2half_rn(x), __float2half_rn(y));
    return *reinterpret_cast<uint32_t*>(&h);
}

// ---------------------------------------------------------------------------
// conversion kernels (bf16x3 splitting) — device symbols never cross host ABI
// ---------------------------------------------------------------------------
__device__ __forceinline__ void split_row(__nv_bfloat16* row, int k, float x) {
    __nv_bfloat16 hi = __float2bfloat16(x);
    __nv_bfloat16 lo = __float2bfloat16(x - __bfloat162float(hi));
    row[k] = hi; row[1280 + k] = hi; row[2560 + k] = lo;
}

__global__ void conv_split_X(const float* __restrict__ src) {
    int i = blockIdx.x * blockDim.x + threadIdx.x;
    if (i >= 2048 * 1280) return;
    int m = i / 1280, k = i - m * 1280;
    split_row(g_Ax + (size_t)m * KP, k, src[i]);
}

__global__ void conv_split_attn() {
    int i = blockIdx.x * blockDim.x + threadIdx.x;
    if (i >= 2048 * 1280) return;
    int m = i / 1280, k = i - m * 1280;
    split_row(g_Aattn + (size_t)m * KP, k, g_attn[i]);
}

__global__ void conv_w_kernel(const float* __restrict__ W, int sel) {
    __shared__ float s[32][33];
    __nv_bfloat16* dst = (sel < 3) ? (g_Bqkv + (size_t)sel * 1280 * KP) : g_Bo;
    int e0 = blockIdx.x * 32, k0 = blockIdx.y * 32;
    int tx = threadIdx.x, ty = threadIdx.y;
    #pragma unroll
    for (int j = 0; j < 4; j++)
        s[ty + j * 8][tx] = W[(k0 + ty + j * 8) * 1280 + e0 + tx];
    __syncthreads();
    #pragma unroll
    for (int j = 0; j < 4; j++) {
        float x = s[tx][ty + j * 8];
        __nv_bfloat16 hi = __float2bfloat16(x);
        __nv_bfloat16 lo = __float2bfloat16(x - __bfloat162float(hi));
        __nv_bfloat16* row = dst + (size_t)(e0 + ty + j * 8) * KP;
        row[k0 + tx] = hi; row[1280 + k0 + tx] = lo; row[2560 + k0 + tx] = hi;
    }
}

// K/V cache fp32 -> fp16 (K row-major padded to 48; V transposed)
__global__ void kv_conv(const float* __restrict__ k_out, const float* __restrict__ v_out) {
    int i = blockIdx.x * blockDim.x + threadIdx.x;
    if (i >= 64 * 2048 * 48) return;
    int bh  = i / (2048 * 48);
    int rem = i - bh * (2048 * 48);
    int key = rem / 48, d = rem - key * 48;
    float kx = 0.f, vx = 0.f;
    if (d < 40) {
        size_t off = ((size_t)bh * 2048 + key) * 40 + d;
        kx = k_out[off]; vx = v_out[off];
    }
    g_Kh[i] = __float2half_rn(kx);
    g_Vt[((size_t)(bh * 48 + d)) * 2048 + key] = __float2half_rn(vx);
}

// ---------------------------------------------------------------------------
// HMMA GEMM mainloop (unchanged from R7, proven)
// ---------------------------------------------------------------------------
__device__ __forceinline__ uint32_t lds32(const char* p) {
    return *reinterpret_cast<const uint32_t*>(p);
}

__device__ __forceinline__ void mma_tile(
    const __nv_bfloat16* __restrict__ A, const __nv_bfloat16* __restrict__ B,
    int m0, int n0, char* smA, char* smB, float acc[2][8][4])
{
    const int tid = threadIdx.x, lane = tid & 31, w = tid >> 5;
    const int wm = w & 3, wn = w >> 2;

    for (int c = 0; c < NCH; c++) {
        #pragma unroll
        for (int i = 0; i < 4; i++) {
            int idx = tid + i * 256;
            int r = idx >> 3, u = idx & 7;
            *reinterpret_cast<float4*>(smA + r * ROWB + u * 16) =
                *reinterpret_cast<const float4*>(A + (size_t)(m0 + r) * KP + c * KC + u * 8);
            *reinterpret_cast<float4*>(smB + r * ROWB + u * 16) =
                *reinterpret_cast<const float4*>(B + (size_t)(n0 + r) * KP + c * KC + u * 8);
        }
        __syncthreads();

        #pragma unroll
        for (int ks = 0; ks < 4; ks++) {
            const int acol2 = (ks * 16 + (lane & 3) * 2) * 2;
            #pragma unroll
            for (int mi = 0; mi < 2; mi++) {
                uint32_t af[4];
                const int ar = wm * 32 + mi * 16 + (lane >> 2);
                af[0] = lds32(smA + ar * ROWB + acol2);
                af[1] = lds32(smA + (ar + 8) * ROWB + acol2);
                af[2] = lds32(smA + ar * ROWB + acol2 + 16);
                af[3] = lds32(smA + (ar + 8) * ROWB + acol2 + 16);
                #pragma unroll
                for (int nb = 0; nb < 4; nb++) {
                    const int br = wn * 64 + nb * 16 + (lane >> 2);
                    uint32_t bf[4];
                    bf[0] = lds32(smB + br * ROWB + acol2);
                    bf[1] = lds32(smB + br * ROWB + acol2 + 16);
                    bf[2] = lds32(smB + (br + 8) * ROWB + acol2);
                    bf[3] = lds32(smB + (br + 8) * ROWB + acol2 + 16);
                    mma16816(acc[mi][2 * nb],     af, bf);
                    mma16816(acc[mi][2 * nb + 1], af, bf + 2);
                }
            }
        }
        __syncthreads();
    }
}

// ---------------------------------------------------------------------------
// GEMM kernel A: fused QKV projection. grid (16, 30)
// ---------------------------------------------------------------------------
__global__ __launch_bounds__(256)
void gemm_qkv_mma(const float* __restrict__ bq, const float* __restrict__ bk,
                  const float* __restrict__ bv,
                  float* __restrict__ k_out, float* __restrict__ v_out)
{
    __shared__ __align__(16) char smA[128 * ROWB];
    __shared__ __align__(16) char smB[128 * ROWB];
    float acc[2][8][4];
    #pragma unroll
    for (int i = 0; i < 2; i++)
        #pragma unroll
        for (int j = 0; j < 8; j++)
            #pragma unroll
            for (int r = 0; r < 4; r++) acc[i][j][r] = 0.f;

    const int m0 = blockIdx.x * 128;
    mma_tile(g_Ax, g_Bqkv, m0, blockIdx.y * 128, smA, smB, acc);

    const int lane = threadIdx.x & 31, w = threadIdx.x >> 5;
    const int wm = w & 3, wn = w >> 2;
    const int which = blockIdx.y / 10;
    const int ebase = (blockIdx.y % 10) * 128 + wn * 64;

    #pragma unroll
    for (int mi = 0; mi < 2; mi++)
        #pragma unroll
        for (int ni = 0; ni < 8; ni++)
            #pragma unroll
            for (int r = 0; r < 4; r++) {
                int m = m0 + wm * 32 + mi * 16 + (lane >> 2) + ((r >> 1) & 1) * 8;
                int e = ebase + ni * 8 + (lane & 3) * 2 + (r & 1);
                int bb = m >> 10, t = m & 1023;
                int h = e / HDIM, d = e - h * HDIM;
                float v = acc[mi][ni][r];
                if (which == 0)
                    g_q[((bb * NHEADS + h) * TGT + t) * HDIM + d] = (v + bq[e]) * SCALING;
                else if (which == 1)
                    k_out[((bb * NHEADS + h) * SEQ + PAST + t) * HDIM + d] = v + bk[e];
                else
                    v_out[((bb * NHEADS + h) * SEQ + PAST + t) * HDIM + d] = v + bv[e];
            }
}

// ---------------------------------------------------------------------------
// GEMM kernel B: output projection. grid (16, 10)
// ---------------------------------------------------------------------------
__global__ __launch_bounds__(256)
void gemm_out_mma(const float* __restrict__ bo, float* __restrict__ out)
{
    __shared__ __align__(16) char smA[128 * ROWB];
    __shared__ __align__(16) char smB[128 * ROWB];
    float acc[2][8][4];
    #pragma unroll
    for (int i = 0; i < 2; i++)
        #pragma unroll
        for (int j = 0; j < 8; j++)
            #pragma unroll
            for (int r = 0; r < 4; r++) acc[i][j][r] = 0.f;

    const int m0 = blockIdx.x * 128;
    const int n0 = blockIdx.y * 128;
    mma_tile(g_Aattn, g_Bo, m0, n0, smA, smB, acc);

    const int lane = threadIdx.x & 31, w = threadIdx.x >> 5;
    const int wm = w & 3, wn = w >> 2;

    #pragma unroll
    for (int mi = 0; mi < 2; mi++)
        #pragma unroll
        for (int ni = 0; ni < 8; ni++)
            #pragma unroll
            for (int r = 0; r < 4; r++) {
                int m = m0 + wm * 32 + mi * 16 + (lane >> 2) + ((r >> 1) & 1) * 8;
                int e = n0 + wn * 64 + ni * 8 + (lane & 3) * 2 + (r & 1);
                out[(size_t)m * EMBED + e] = acc[mi][ni][r] + bo[e];
            }
}

// ---------------------------------------------------------------------------
// past K/V copy
// ---------------------------------------------------------------------------
__global__ void copy_past_kernel(const float4* __restrict__ pk,
                                 const float4* __restrict__ pv,
                                 float4* __restrict__ ko,
                                 float4* __restrict__ vo) {
    const int total  = BSZV * NHEADS * PAST * HDIM / 4;
    int i = blockIdx.x * blockDim.x + threadIdx.x;
    if (i >= total) return;
    const int per_bh = PAST * HDIM / 4;
    int bh = i / per_bh;
    int r  = i - bh * per_bh;
    int o  = bh * (SEQ * HDIM / 4) + r;
    ko[o] = pk[i];
    vo[o] = pv[i];
}

// ---------------------------------------------------------------------------
// HMMA flash attention. grid (64 bh, 8 qtiles of 128), 256 threads (8 warps).
// Warp w owns rows w*16..+15. Chunks of 128 keys.
// QK: S += Qhi*Kh + Qlo*Kh (2-term fp16 split). PV: O += Phi*Vh + Plo*Vh.
// Zero kernel arguments — all state via device symbols.
// ---------------------------------------------------------------------------
__global__ __launch_bounds__(256) void attn_hmma()
{
    __shared__ __align__(16) __half Kbuf[128 * 56];    // [key][dim pad56]
    __shared__ __align__(16) __half Vbuf[48 * 136];    // [dim][key pad136]

    const int bh = blockIdx.x;
    const int qt = blockIdx.y;
    const int b  = bh >> 5, h = bh & 31;
    const int tid = threadIdx.x, lane = tid & 31, w = tid >> 5;
    const int g = lane >> 2, tig = lane & 3;

    // ---- Q fragments (hi/lo fp16), rows t0=qt*128+w*16+g and t0+8 ----
    uint32_t qhi[3][4], qlo[3][4];
    {
        const int t0 = qt * 128 + w * 16 + g;
        const float* Q0 = g_q + ((size_t)bh * 1024 + t0) * 40;
        const float* Q1 = Q0 + 8 * 40;
        #pragma unroll
        for (int ks = 0; ks < 3; ks++)
            #pragma unroll
            for (int j = 0; j < 2; j++) {
                int k0 = ks * 16 + j * 8 + tig * 2;
                float xa0 = (k0     < 40) ? Q0[k0]     : 0.f;
                float xa1 = (k0 + 1 < 40) ? Q0[k0 + 1] : 0.f;
                float xb0 = (k0     < 40) ? Q1[k0]     : 0.f;
                float xb1 = (k0 + 1 < 40) ? Q1[k0 + 1] : 0.f;
                float ha0 = __half2float(__float2half_rn(xa0));
                float ha1 = __half2float(__float2half_rn(xa1));
                float hb0 = __half2float(__float2half_rn(xb0));
                float hb1 = __half2float(__float2half_rn(xb1));
                qhi[ks][j * 2]     = packh(ha0, ha1);
                qhi[ks][j * 2 + 1] = packh(hb0, hb1);
                qlo[ks][j * 2]     = packh(xa0 - ha0, xa1 - ha1);
                qlo[ks][j * 2 + 1] = packh(xb0 - hb0, xb1 - hb1);
            }
    }

    float m_r[2] = { -1e30f, -1e30f };
    float l_r[2] = { 0.f, 0.f };
    float O[6][4];
    #pragma unroll
    for (int vt = 0; vt < 6; vt++)
        #pragma unroll
        for (int r = 0; r < 4; r++) O[vt][r] = 0.f;

    for (int ch = 0; ch < 16; ch++) {
        // ---- load K chunk [128 x 48] and V^T chunk [48 x 128] ----
        {
            const uint32_t* Ks = (const uint32_t*)(g_Kh + ((size_t)bh * 2048 + ch * 128) * 48);
            uint32_t* Kd = (uint32_t*)Kbuf;
            #pragma unroll
            for (int i = 0; i < 12; i++) {
                int idx = tid + i * 256;
                int r = idx / 24, cw = idx - r * 24;
                Kd[r * 28 + cw] = Ks[r * 24 + cw];
            }
            #pragma unroll
            for (int i = 0; i < 12; i++) {
                int idx = tid + i * 256;
                int d = idx >> 6, kw = idx & 63;
                ((uint32_t*)Vbuf)[d * 68 + kw] =
                    ((const uint32_t*)(g_Vt + ((size_t)(bh * 48 + d)) * 2048 + ch * 128))[kw];
            }
        }
        __syncthreads();

        // ---- S = Q * K^T for 16 rows x 128 keys ----
        float S[16][4];
        #pragma unroll
        for (int nt = 0; nt < 16; nt++)
            #pragma unroll
            for (int r = 0; r < 4; r++) S[nt][r] = 0.f;

        #pragma unroll
        for (int ks = 0; ks < 3; ks++)
            #pragma unroll
            for (int nt = 0; nt < 16; nt++) {
                uint32_t bfr[2];
                const __half* bp = Kbuf + (nt * 8 + g) * 56 + ks * 16 + tig * 2;
                bfr[0] = *(const uint32_t*)bp;
                bfr[1] = *(const uint32_t*)(bp + 8);
                mma16816h(S[nt], qhi[ks], bfr);
                mma16816h(S[nt], qlo[ks], bfr);
            }

        // ---- online softmax (rows g and g+8; reduce across 4-lane group) ----
        #pragma unroll
        for (int rh = 0; rh < 2; rh++) {
            float mx = -1e30f;
            #pragma unroll
            for (int nt = 0; nt < 16; nt++)
                mx = fmaxf(mx, fmaxf(S[nt][rh * 2], S[nt][rh * 2 + 1]));
            mx = fmaxf(mx, __shfl_xor_sync(0xffffffffu, mx, 1));
            mx = fmaxf(mx, __shfl_xor_sync(0xffffffffu, mx, 2));
            float mn   = fmaxf(m_r[rh], mx);
            float corr = __expf(m_r[rh] - mn);
            m_r[rh] = mn;
            float ls = 0.f;
            #pragma unroll
            for (int nt = 0; nt < 16; nt++) {
                float p0 = __expf(S[nt][rh * 2] - mn);
                float p1 = __expf(S[nt][rh * 2 + 1] - mn);
                S[nt][rh * 2] = p0; S[nt][rh * 2 + 1] = p1;
                ls += p0 + p1;
            }
            ls += __shfl_xor_sync(0xffffffffu, ls, 1);
            ls += __shfl_xor_sync(0xffffffffu, ls, 2);
            l_r[rh] = l_r[rh] * corr + ls;
            #pragma unroll
            for (int vt = 0; vt < 6; vt++) {
                O[vt][rh * 2] *= corr; O[vt][rh * 2 + 1] *= corr;
            }
        }

        // ---- O += P * V (P split hi/lo, V fp16) ----
        #pragma unroll
        for (int kk = 0; kk < 8; kk++) {
            uint32_t ahi[4], alo[4];
            #pragma unroll
            for (int p = 0; p < 2; p++) {
                const float* Sp = S[2 * kk + p];
                float h0 = __half2float(__float2half_rn(Sp[0]));
                float h1 = __half2float(__float2half_rn(Sp[1]));
                float h2 = __half2float(__float2half_rn(Sp[2]));
                float h3 = __half2float(__float2half_rn(Sp[3]));
                ahi[p * 2]     = packh(h0, h1);
                ahi[p * 2 + 1] = packh(h2, h3);
                alo[p * 2]     = packh(Sp[0] - h0, Sp[1] - h1);
                alo[p * 2 + 1] = packh(Sp[2] - h2, Sp[3] - h3);
            }
            #pragma unroll
            for (int vt = 0; vt < 6; vt++) {
                uint32_t bfr[2];
                const __half* bp = Vbuf + (vt * 8 + g) * 136 + kk * 16 + tig * 2;
                bfr[0] = *(const uint32_t*)bp;
                bfr[1] = *(const uint32_t*)(bp + 8);
                mma16816h(O[vt], ahi, bfr);
                mma16816h(O[vt], alo, bfr);
            }
        }
        __syncthreads();
    }

    // ---- epilogue: O / l -> g_attn ----
    #pragma unroll
    for (int rh = 0; rh < 2; rh++) {
        int t = qt * 128 + w * 16 + g + rh * 8;
        float inv = 1.f / l_r[rh];
        float* dst = g_attn + ((size_t)b * 1024 + t) * 1280 + h * 40;
        #pragma unroll
        for (int vt = 0; vt < 6; vt++) {
            int d0 = vt * 8 + tig * 2;
            if (d0 < 40)     dst[d0]     = O[vt][rh * 2] * inv;
            if (d0 + 1 < 40) dst[d0 + 1] = O[vt][rh * 2 + 1] * inv;
        }
    }
}

// ---------------------------------------------------------------------------
extern "C" void kernel_launch(void* const* d_in, const int* in_sizes, int n_in,
                              void* d_out, int out_size) {
    const float* X  = (const float*)d_in[0];
    const float* pk = (const float*)d_in[1];
    const float* pv = (const float*)d_in[2];
    const float* Wq = (const float*)d_in[3];
    const float* bq = (const float*)d_in[4];
    const float* Wk = (const float*)d_in[5];
    const float* bk = (const float*)d_in[6];
    const float* Wv = (const float*)d_in[7];
    const float* bv = (const float*)d_in[8];
    const float* Wo = (const float*)d_in[9];
    const float* bo = (const float*)d_in[10];

    float* out      = (float*)d_out;
    float* attn_out = out;
    float* k_out    = out + (size_t)BSZV * TGT * EMBED;
    float* v_out    = k_out + (size_t)BSZV * NHEADS * SEQ * HDIM;

    // 1) past KV copy
    {
        int total = BSZV * NHEADS * PAST * HDIM / 4;
        copy_past_kernel<<<(total + 255) / 256, 256>>>(
            (const float4*)pk, (const float4*)pv, (float4*)k_out, (float4*)v_out);
    }
    // 2) conversions for projection GEMM
    conv_split_X<<<(2048 * 1280 + 255) / 256, 256>>>(X);
    {
        dim3 g(40, 40), b2(32, 8);
        conv_w_kernel<<<g, b2>>>(Wq, 0);
        conv_w_kernel<<<g, b2>>>(Wk, 1);
        conv_w_kernel<<<g, b2>>>(Wv, 2);
        conv_w_kernel<<<g, b2>>>(Wo, 3);
    }
    // 3) fused QKV projection (HMMA)
    gemm_qkv_mma<<<dim3(16, 30), 256>>>(bq, bk, bv, k_out, v_out);
    // 4) K/V cache -> fp16 (K padded, V transposed)
    kv_conv<<<(64 * 2048 * 48 + 255) / 256, 256>>>(k_out, v_out);
    // 5) attention (HMMA flash)
    attn_hmma<<<dim3(64, 8), 256>>>();
    // 6) output projection (HMMA)
    conv_split_attn<<<(2048 * 1280 + 255) / 256, 256>>>();
    gemm_out_mma<<<dim3(16, 10), 256>>>(bo, attn_out);
}